// round 7
// baseline (speedup 1.0000x reference)
#include <cuda_runtime.h>

// Multi-class hinge (Crammer-Singer) loss, summed over batch.
// outputs: [N, C] fp32, labels: [N] int32, out: scalar fp32.
//
// sum_{i,j != y_i} max(outputs[i,j] - outputs[i,y_i] + 1, 0)
// The j == y_i term contributes exactly 1.0: sum over all j, subtract 1/row.
//
// 2 rows per CTA, 512 threads (half-block per row). Ground-truth value is
// published from the owning thread's registers via smem (no dependent
// gather). Kernel is LTS-cap bound (~6300 B/cyc path-independent), so this
// round only consolidates per-CTA overhead: half the CTAs, half the atomics.

static constexpr int C_DIM    = 4096;
static constexpr int THREADS  = 512;         // 256 threads per row, 2 rows
static constexpr int TPR      = 256;         // threads per row
static constexpr int WARPS    = THREADS / 32;

__global__ void zero_out_kernel(float* out) {
    if (threadIdx.x == 0) out[0] = 0.0f;
}

__global__ __launch_bounds__(THREADS) void hinge_loss_kernel(
    const float* __restrict__ outputs,
    const int* __restrict__ labels,
    float* __restrict__ out)
{
    const int tid  = threadIdx.x;
    const int half = tid >> 8;                // 0 or 1: which row
    const int rtid = tid & (TPR - 1);         // thread index within the row
    const int row  = (blockIdx.x << 1) + half;

    const float4* rowp =
        reinterpret_cast<const float4*>(outputs + (size_t)row * C_DIM);

    // All five loads below are independent — issue together.
    const int lab = __ldg(labels + row);
    float4 v0 = rowp[rtid];
    float4 v1 = rowp[rtid + TPR];
    float4 v2 = rowp[rtid + 2 * TPR];
    float4 v3 = rowp[rtid + 3 * TPR];

    // Broadcast the ground-truth value from the owning thread's registers.
    __shared__ float sg[2];
    const int f = lab >> 2;                   // float4 index within the row
    if (rtid == (f & (TPR - 1))) {
        const int chunk = f >> 8;             // which of v0..v3
        float4 v = (chunk == 0) ? v0 : (chunk == 1) ? v1 : (chunk == 2) ? v2 : v3;
        const float* e = reinterpret_cast<const float*>(&v);
        sg[half] = e[lab & 3];
    }
    __syncthreads();
    const float t = 1.0f - sg[half];          // margin = max(o + t, 0)

    float s = 0.0f;
    s += fmaxf(v0.x + t, 0.0f); s += fmaxf(v0.y + t, 0.0f);
    s += fmaxf(v0.z + t, 0.0f); s += fmaxf(v0.w + t, 0.0f);
    s += fmaxf(v1.x + t, 0.0f); s += fmaxf(v1.y + t, 0.0f);
    s += fmaxf(v1.z + t, 0.0f); s += fmaxf(v1.w + t, 0.0f);
    s += fmaxf(v2.x + t, 0.0f); s += fmaxf(v2.y + t, 0.0f);
    s += fmaxf(v2.z + t, 0.0f); s += fmaxf(v2.w + t, 0.0f);
    s += fmaxf(v3.x + t, 0.0f); s += fmaxf(v3.y + t, 0.0f);
    s += fmaxf(v3.z + t, 0.0f); s += fmaxf(v3.w + t, 0.0f);

    // warp reduce
    #pragma unroll
    for (int o = 16; o > 0; o >>= 1)
        s += __shfl_xor_sync(0xFFFFFFFFu, s, o);

    __shared__ float ws[WARPS];
    if ((tid & 31) == 0) ws[tid >> 5] = s;
    __syncthreads();

    if (tid == 0) {
        float v = ws[0];
        #pragma unroll
        for (int w = 1; w < WARPS; w++) v += ws[w];
        // subtract the j == label contribution (exactly 1.0 per row, 2 rows)
        atomicAdd(out, v - 2.0f);
    }
}

extern "C" void kernel_launch(void* const* d_in, const int* in_sizes, int n_in,
                              void* d_out, int out_size) {
    const float* outputs = (const float*)d_in[0];
    const int* labels = (const int*)d_in[1];
    float* out = (float*)d_out;

    const int N = in_sizes[1];          // 16384 labels

    zero_out_kernel<<<1, 32>>>(out);
    hinge_loss_kernel<<<N / 2, THREADS>>>(outputs, labels, out);
}

// round 8
// speedup vs baseline: 1.0211x; 1.0211x over previous
#include <cuda_runtime.h>

// Multi-class hinge (Crammer-Singer) loss, summed over batch.
// outputs: [N, C] fp32, labels: [N] int32, out: scalar fp32.
//
// sum_{i,j != y_i} max(outputs[i,j] - outputs[i,y_i] + 1, 0)
// The j == y_i term contributes exactly 1.0: sum over all j, subtract 1/row.
//
// 2 rows per CTA, 512 threads (256 per row) — best measured kernel config
// (40.3us, DRAM 85.4%). Ground-truth value published from the owning
// thread's registers via smem (no dependent gather). Output zeroed via a
// graph-capturable cudaMemsetAsync instead of a kernel launch.

static constexpr int C_DIM    = 4096;
static constexpr int THREADS  = 512;         // 256 threads per row, 2 rows
static constexpr int TPR      = 256;         // threads per row
static constexpr int WARPS    = THREADS / 32;

__global__ __launch_bounds__(THREADS) void hinge_loss_kernel(
    const float* __restrict__ outputs,
    const int* __restrict__ labels,
    float* __restrict__ out)
{
    const int tid  = threadIdx.x;
    const int half = tid >> 8;                // 0 or 1: which row
    const int rtid = tid & (TPR - 1);         // thread index within the row
    const int row  = (blockIdx.x << 1) + half;

    const float4* rowp =
        reinterpret_cast<const float4*>(outputs + (size_t)row * C_DIM);

    // All five loads below are independent — issue together.
    const int lab = __ldg(labels + row);
    float4 v0 = rowp[rtid];
    float4 v1 = rowp[rtid + TPR];
    float4 v2 = rowp[rtid + 2 * TPR];
    float4 v3 = rowp[rtid + 3 * TPR];

    // Broadcast the ground-truth value from the owning thread's registers.
    __shared__ float sg[2];
    const int f = lab >> 2;                   // float4 index within the row
    if (rtid == (f & (TPR - 1))) {
        const int chunk = f >> 8;             // which of v0..v3
        float4 v = (chunk == 0) ? v0 : (chunk == 1) ? v1 : (chunk == 2) ? v2 : v3;
        const float* e = reinterpret_cast<const float*>(&v);
        sg[half] = e[lab & 3];
    }
    __syncthreads();
    const float t = 1.0f - sg[half];          // margin = max(o + t, 0)

    float s = 0.0f;
    s += fmaxf(v0.x + t, 0.0f); s += fmaxf(v0.y + t, 0.0f);
    s += fmaxf(v0.z + t, 0.0f); s += fmaxf(v0.w + t, 0.0f);
    s += fmaxf(v1.x + t, 0.0f); s += fmaxf(v1.y + t, 0.0f);
    s += fmaxf(v1.z + t, 0.0f); s += fmaxf(v1.w + t, 0.0f);
    s += fmaxf(v2.x + t, 0.0f); s += fmaxf(v2.y + t, 0.0f);
    s += fmaxf(v2.z + t, 0.0f); s += fmaxf(v2.w + t, 0.0f);
    s += fmaxf(v3.x + t, 0.0f); s += fmaxf(v3.y + t, 0.0f);
    s += fmaxf(v3.z + t, 0.0f); s += fmaxf(v3.w + t, 0.0f);

    // warp reduce
    #pragma unroll
    for (int o = 16; o > 0; o >>= 1)
        s += __shfl_xor_sync(0xFFFFFFFFu, s, o);

    __shared__ float ws[WARPS];
    if ((tid & 31) == 0) ws[tid >> 5] = s;
    __syncthreads();

    if (tid == 0) {
        float v = ws[0];
        #pragma unroll
        for (int w = 1; w < WARPS; w++) v += ws[w];
        // subtract the j == label contribution (exactly 1.0 per row, 2 rows)
        atomicAdd(out, v - 2.0f);
    }
}

extern "C" void kernel_launch(void* const* d_in, const int* in_sizes, int n_in,
                              void* d_out, int out_size) {
    const float* outputs = (const float*)d_in[0];
    const int* labels = (const int*)d_in[1];
    float* out = (float*)d_out;

    const int N = in_sizes[1];          // 16384 labels

    cudaMemsetAsync(out, 0, sizeof(float));
    hinge_loss_kernel<<<N / 2, THREADS>>>(outputs, labels, out);
}